// round 8
// baseline (speedup 1.0000x reference)
#include <cuda_runtime.h>
#include <cuda_bf16.h>
#include <math.h>

// ---------------------------------------------------------------------------
// RAFT-SLAM update block, fp32, implicit-GEMM convs with packed fma.rn.f32x2.
// Multi-job launches: blockIdx.y selects {weights,bias,out,Cin,act} so convs
// sharing one input tensor run in a single launch. GRU output fused into the
// q-final conv epilogue; q conv split into an r-independent partial (runs
// with z/r) and a short K=1152 completion.
// ---------------------------------------------------------------------------

#define Hh 60
#define Ww 80
#define HW 4800
#define BN 24

#define ACT_NONE 0
#define ACT_RELU 1
#define ACT_SIG  2
#define ACT_GRUQ 3   // h' = (1-z)*h + z*tanh(acc + qpart)

typedef unsigned long long u64;

// ---------------- scratch (static device memory; no cudaMalloc allowed) ----
__device__ float g_hx[BN * 448 * HW];   // [h or r*h | inp | corrfeat | flowfeat]
__device__ float g_t0[BN * 128 * HW];   // ce1 out, later d1 out
__device__ float g_t1[BN * 128 * HW];   // fe1 out, later w1 out
__device__ float g_z [BN * 128 * HW];
__device__ float g_r [BN * 128 * HW];
__device__ float g_q [BN * 128 * HW];   // q partial (x-channel contribution)
__device__ float g_zbias[128];          // zero-initialized per CUDA semantics

// packed 2x fp32 FMA (sm_103a; ptxas never auto-fuses this from C++)
__device__ __forceinline__ u64 ffma2(u64 a, u64 b, u64 c) {
    u64 d;
    asm("fma.rn.f32x2 %0, %1, %2, %3;" : "=l"(d) : "l"(a), "l"(b), "l"(c));
    return d;
}
__device__ __forceinline__ float lo32f(u64 v) { return __uint_as_float((unsigned)(v)); }
__device__ __forceinline__ float hi32f(u64 v) { return __uint_as_float((unsigned)(v >> 32)); }

// ---------------- job descriptor -------------------------------------------
struct Job {
    const float* wt;      // weight matrix base
    const float* bias;
    float*       out;
    int Cin;              // input channels this job consumes
    int in_choff;         // channel offset into shared input tensor
    int out_choff;        // channel offset into output tensor
    int wk_stride;        // weight row stride (full K of original conv)
    int wk_off;           // k offset into weight row
    int act;
};

// ---------------- implicit GEMM conv ---------------------------------------
// Tiles: TM=128 (cout), TN=128 (pixels), TK=16. 256 threads, 8x8 microtile.
// As2 holds weights pre-duplicated as (w,w) u64 pairs (no packing in loop).
// Double-buffered smem (48KB exactly). 2 CTAs/SM.
// NOTE: __align__(16) is load-bearing — the inner loop issues LDS.128 through
// ulonglong2*, and sm_103a traps (err715) on misaligned wide ops.
#define TM 128
#define TN 128
#define TK 16

template<int KH, int KW, int PAD>
__global__ __launch_bounds__(256, 2)
void conv_igemm(const float* __restrict__ in,
                Job j0, Job j1, Job j2,
                int Cout, int in_bstride, int out_bstride,
                const float* __restrict__ zbuf,
                const float* __restrict__ qbuf,
                const float* __restrict__ hbuf)
{
    const Job jb = (blockIdx.y == 0) ? j0 : ((blockIdx.y == 1) ? j1 : j2);
    const int K  = jb.Cin * KH * KW;
    const int bn = blockIdx.z;
    const int n0 = blockIdx.x * TN;
    const float* wt  = jb.wt;
    const float* inb = in + (size_t)bn * in_bstride + (size_t)jb.in_choff * HW;

    __shared__ __align__(16) u64   As2[2][TK][TM];   // 32KB
    __shared__ __align__(16) float Bs [2][TK][TN];   // 16KB

    const int tid = threadIdx.x;

    // B-load mapping: element j (0..7): k_local = j*2 + tid/128, n_local = tid%128
    const int bn_local = tid & 127;
    const int bk_base  = tid >> 7;
    const int n_glob   = n0 + bn_local;
    const int py = n_glob / Ww;
    const int px = n_glob % Ww;
    const bool nvalid = (n_glob < HW);

    // halo validity bitmasks (bit t set => py+t-PAD / px+t-PAD in range)
    unsigned rowmask = 0, colmask = 0;
    #pragma unroll
    for (int t = 0; t < KH; t++) {
        int iy = py + t - PAD;
        if (iy >= 0 && iy < Hh) rowmask |= (1u << t);
    }
    #pragma unroll
    for (int t = 0; t < KW; t++) {
        int ix = px + t - PAD;
        if (ix >= 0 && ix < Ww) colmask |= (1u << t);
    }
    if (!nvalid) { rowmask = 0; colmask = 0; }
    // base pointer at (py-PAD, px-PAD)
    const float* ibase = inb + (py - PAD) * Ww + (px - PAD);

    // A-load mapping: element j (0..7): k_local = tid%16, m_local = j*16 + tid/16
    const int ak      = tid & 15;
    const int am_base = tid >> 4;

    // compute mapping
    const int tr = tid >> 4;   // cout rows tr*8..+7
    const int tc = tid & 15;   // pixels tc*8..+7

    u64 acc2[8][4];
    #pragma unroll
    for (int i = 0; i < 8; i++)
        #pragma unroll
        for (int j = 0; j < 4; j++) acc2[i][j] = 0ull;

    auto gatherA = [&](int k0, float (&ar)[8]) {
        #pragma unroll
        for (int j = 0; j < 8; j++) {
            int m = am_base + j * 16;
            int k = k0 + ak;
            float v = 0.f;
            if (k < K && m < Cout)
                v = wt[(size_t)m * jb.wk_stride + jb.wk_off + k];
            ar[j] = v;
        }
    };
    auto gatherB = [&](int k0, float (&br)[8]) {
        #pragma unroll
        for (int j = 0; j < 8; j++) {
            int k = k0 + bk_base + j * 2;
            float v = 0.f;
            if (KH == 1 && KW == 1) {
                if (k < K && nvalid)
                    v = ibase[(size_t)k * HW];
            } else {
                int ci  = k / (KH * KW);
                int rem = k - ci * (KH * KW);
                int ky  = rem / KW;
                int kx  = rem - ky * KW;
                bool ok = (k < K) & (((rowmask >> ky) & (colmask >> kx)) & 1u);
                if (ok)
                    v = ibase[(size_t)ci * HW + ky * Ww + kx];
            }
            br[j] = v;
        }
    };
    auto stage = [&](int buf, const float (&ar)[8], const float (&br)[8]) {
        #pragma unroll
        for (int j = 0; j < 8; j++) {
            unsigned bits = __float_as_uint(ar[j]);
            As2[buf][ak][am_base + j * 16] = ((u64)bits << 32) | (u64)bits;
        }
        #pragma unroll
        for (int j = 0; j < 8; j++)
            Bs[buf][bk_base + j * 2][bn_local] = br[j];
    };

    // ---- prologue -----------------------------------------------------------
    {
        float ar[8], br[8];
        gatherA(0, ar); gatherB(0, br);
        stage(0, ar, br);
    }
    __syncthreads();

    int buf = 0;
    for (int k0 = 0; k0 < K; k0 += TK) {
        const bool more = (k0 + TK < K);
        float ar[8], br[8];
        if (more) { gatherA(k0 + TK, ar); gatherB(k0 + TK, br); }

        // ---- compute: 16 k-steps x (8x4) FFMA2, LDS.128 reads
        #pragma unroll
        for (int kk = 0; kk < TK; kk++) {
            const ulonglong2* ap2 = (const ulonglong2*)&As2[buf][kk][tr * 8];
            ulonglong2 av0 = ap2[0], av1 = ap2[1], av2 = ap2[2], av3 = ap2[3];
            const ulonglong2* bp2 = (const ulonglong2*)&Bs[buf][kk][tc * 8];
            ulonglong2 bv0 = bp2[0], bv1 = bp2[1];
            u64 a[8] = {av0.x, av0.y, av1.x, av1.y, av2.x, av2.y, av3.x, av3.y};
            u64 b[4] = {bv0.x, bv0.y, bv1.x, bv1.y};
            #pragma unroll
            for (int i = 0; i < 8; i++)
                #pragma unroll
                for (int j = 0; j < 4; j++)
                    acc2[i][j] = ffma2(a[i], b[j], acc2[i][j]);
        }

        if (more) stage(buf ^ 1, ar, br);
        __syncthreads();
        buf ^= 1;
    }

    // ---- epilogue: bias + activation (+GRU fusion) + float4 store ----------
    float* outb = jb.out + (size_t)bn * out_bstride + (size_t)jb.out_choff * HW;
    const int act = jb.act;
    #pragma unroll
    for (int i = 0; i < 8; i++) {
        int m = tr * 8 + i;
        if (m >= Cout) continue;
        float bv = jb.bias[m];
        #pragma unroll
        for (int jj = 0; jj < 2; jj++) {
            int n = n0 + tc * 8 + jj * 4;
            if (n + 3 >= HW) continue;
            float vals[4] = { lo32f(acc2[i][jj * 2]),     hi32f(acc2[i][jj * 2]),
                              lo32f(acc2[i][jj * 2 + 1]), hi32f(acc2[i][jj * 2 + 1]) };
            float4 v;
            float* vp = (float*)&v;
            #pragma unroll
            for (int j = 0; j < 4; j++) {
                float x = vals[j] + bv;
                if (act == ACT_RELU)      x = fmaxf(x, 0.f);
                else if (act == ACT_SIG)  x = 1.f / (1.f + expf(-x));
                else if (act == ACT_GRUQ) {
                    size_t e = (size_t)bn * (128 * HW) + (size_t)m * HW + (n + j);
                    float q = tanhf(x + qbuf[e]);
                    float z = zbuf[e];
                    x = (1.f - z) * hbuf[e] + z * q;
                }
                vp[j] = x;
            }
            *(float4*)&outb[(size_t)m * HW + n] = v;
        }
    }
}

// ---------------- 128 -> 3 head conv (3x3, pad 1), fused NHWC transpose ----
template<int ACT>
__global__ __launch_bounds__(128)
void head_conv3(const float* __restrict__ in, const float* __restrict__ wt,
                const float* __restrict__ bias, float* __restrict__ out)
{
    __shared__ float ws[3 * 128 * 9];
    for (int i = threadIdx.x; i < 3 * 128 * 9; i += blockDim.x) ws[i] = wt[i];
    __syncthreads();

    const int bn = blockIdx.y;
    const int p  = blockIdx.x * blockDim.x + threadIdx.x;
    if (p >= HW) return;
    const int y = p / Ww, x = p % Ww;
    const float* inb = in + (size_t)bn * 128 * HW;

    float a0 = bias[0], a1 = bias[1], a2 = bias[2];
    for (int ci = 0; ci < 128; ci++) {
        const float* ip = inb + (size_t)ci * HW;
        #pragma unroll
        for (int ky = 0; ky < 3; ky++) {
            int iy = y + ky - 1;
            if (iy < 0 || iy >= Hh) continue;
            #pragma unroll
            for (int kx = 0; kx < 3; kx++) {
                int ix = x + kx - 1;
                if (ix < 0 || ix >= Ww) continue;
                float v = __ldg(&ip[iy * Ww + ix]);
                int t = ci * 9 + ky * 3 + kx;
                a0 = fmaf(ws[t],            v, a0);
                a1 = fmaf(ws[1152 + t],     v, a1);
                a2 = fmaf(ws[2 * 1152 + t], v, a2);
            }
        }
    }
    if (ACT == ACT_SIG) {
        a0 = 1.f / (1.f + expf(-a0));
        a1 = 1.f / (1.f + expf(-a1));
        a2 = 1.f / (1.f + expf(-a2));
    }
    size_t o = ((size_t)bn * HW + p) * 3;   // NHWC
    out[o + 0] = a0; out[o + 1] = a1; out[o + 2] = a2;
}

// ---------------- elementwise kernels ---------------------------------------
__global__ void pack_hx_kernel(const float* __restrict__ net,
                               const float* __restrict__ inp)
{
    int idx = blockIdx.x * blockDim.x + threadIdx.x;
    const int per = 128 * HW;
    if (idx >= BN * per) return;
    int bn = idx / per;
    int r  = idx - bn * per;
    float* hx = g_hx + (size_t)bn * 448 * HW;
    hx[r]            = net[idx];
    hx[128 * HW + r] = inp[idx];
}

__global__ void rh_kernel(const float* __restrict__ net)
{
    int idx = blockIdx.x * blockDim.x + threadIdx.x;
    const int per = 128 * HW;
    if (idx >= BN * per) return;
    int bn = idx / per;
    int r  = idx - bn * per;
    g_hx[(size_t)bn * 448 * HW + r] = g_r[idx] * net[idx];
}

// ---------------- launch graph ----------------------------------------------
static inline Job mkjob(const float* w, const float* b, float* o,
                        int cin, int ichoff, int ochoff,
                        int wks, int wko, int act)
{
    Job j; j.wt = w; j.bias = b; j.out = o; j.Cin = cin; j.in_choff = ichoff;
    j.out_choff = ochoff; j.wk_stride = wks; j.wk_off = wko; j.act = act;
    return j;
}

extern "C" void kernel_launch(void* const* d_in, const int* in_sizes, int n_in,
                              void* d_out, int out_size)
{
    const float* net   = (const float*)d_in[0];
    const float* inp   = (const float*)d_in[1];
    const float* corr  = (const float*)d_in[2];
    const float* flow  = (const float*)d_in[3];
    const float* w_ce1 = (const float*)d_in[4];   const float* b_ce1 = (const float*)d_in[5];
    const float* w_ce2 = (const float*)d_in[6];   const float* b_ce2 = (const float*)d_in[7];
    const float* w_fe1 = (const float*)d_in[8];   const float* b_fe1 = (const float*)d_in[9];
    const float* w_fe2 = (const float*)d_in[10];  const float* b_fe2 = (const float*)d_in[11];
    const float* w_z   = (const float*)d_in[12];  const float* b_z   = (const float*)d_in[13];
    const float* w_r   = (const float*)d_in[14];  const float* b_r   = (const float*)d_in[15];
    const float* w_q   = (const float*)d_in[16];  const float* b_q   = (const float*)d_in[17];
    const float* w_d1  = (const float*)d_in[18];  const float* b_d1  = (const float*)d_in[19];
    const float* w_d2  = (const float*)d_in[20];  const float* b_d2  = (const float*)d_in[21];
    const float* w_w1  = (const float*)d_in[22];  const float* b_w1  = (const float*)d_in[23];
    const float* w_w2  = (const float*)d_in[24];  const float* b_w2  = (const float*)d_in[25];

    float* out_net   = (float*)d_out;                       // (BN,128,H,W)
    float* out_delta = out_net + (size_t)BN * 128 * HW;     // (BN,H,W,3)
    float* out_wgt   = out_delta + (size_t)BN * 3 * HW;     // (BN,H,W,3)

    float *hx, *t0, *t1, *zb, *rb, *qb, *zbias;
    cudaGetSymbolAddress((void**)&hx, g_hx);
    cudaGetSymbolAddress((void**)&t0, g_t0);
    cudaGetSymbolAddress((void**)&t1, g_t1);
    cudaGetSymbolAddress((void**)&zb, g_z);
    cudaGetSymbolAddress((void**)&rb, g_r);
    cudaGetSymbolAddress((void**)&qb, g_q);
    cudaGetSymbolAddress((void**)&zbias, g_zbias);

    const dim3 blk(256);
    const int  NX = (HW + TN - 1) / TN;          // 38
    const dim3 g1(NX, 1, BN);
    const dim3 g2(NX, 2, BN);
    const dim3 g3(NX, 3, BN);
    const int EW = 256;
    const int NE = BN * 128 * HW;
    const int EG = (NE + EW - 1) / EW;

    // encoders
    {
        Job j = mkjob(w_ce1, b_ce1, t0, 197, 0, 0, 197, 0, ACT_RELU);
        conv_igemm<1,1,0><<<g1, blk>>>(corr, j, j, j, 128, 197*HW, 128*HW, 0, 0, 0);
    }
    {
        Job j = mkjob(w_ce2, b_ce2, hx, 128, 0, 256, 1152, 0, ACT_RELU);
        conv_igemm<3,3,1><<<g1, blk>>>(t0, j, j, j, 128, 128*HW, 448*HW, 0, 0, 0);
    }
    {
        Job j = mkjob(w_fe1, b_fe1, t1, 3, 0, 0, 147, 0, ACT_RELU);
        conv_igemm<7,7,3><<<g1, blk>>>(flow, j, j, j, 128, 3*HW, 128*HW, 0, 0, 0);
    }
    {
        Job j = mkjob(w_fe2, b_fe2, hx, 128, 0, 384, 1152, 0, ACT_RELU);
        conv_igemm<3,3,1><<<g1, blk>>>(t1, j, j, j, 64, 128*HW, 448*HW, 0, 0, 0);
    }

    // hx[0:128]=h, hx[128:256]=inp
    pack_hx_kernel<<<EG, EW>>>(net, inp);

    // gates: z, r (K=4032) + q-partial over x channels (K=2880) in ONE launch
    {
        Job jz = mkjob(w_z, b_z, zb, 448, 0, 0, 4032, 0, ACT_SIG);
        Job jr = mkjob(w_r, b_r, rb, 448, 0, 0, 4032, 0, ACT_SIG);
        Job jq = mkjob(w_q, b_q, qb, 320, 128, 0, 4032, 1152, ACT_NONE);
        conv_igemm<3,3,1><<<g3, blk>>>(hx, jz, jr, jq, 128, 448*HW, 128*HW, 0, 0, 0);
    }
    rh_kernel<<<EG, EW>>>(net);                   // hx[0:128] = r*h

    // q completion over r*h (K=1152) with fused GRU output -> out_net
    {
        Job j = mkjob(w_q, zbias, out_net, 128, 0, 0, 4032, 0, ACT_GRUQ);
        conv_igemm<3,3,1><<<g1, blk>>>(hx, j, j, j, 128, 448*HW, 128*HW, zb, qb, net);
    }

    // heads: d1 and w1 share input h' -> one dual launch
    {
        Job jd = mkjob(w_d1, b_d1, t0, 128, 0, 0, 1152, 0, ACT_RELU);
        Job jw = mkjob(w_w1, b_w1, t1, 128, 0, 0, 1152, 0, ACT_RELU);
        conv_igemm<3,3,1><<<g2, blk>>>(out_net, jd, jw, jw, 128, 128*HW, 128*HW, 0, 0, 0);
    }

    dim3 hgrd((HW + 127) / 128, BN);
    head_conv3<ACT_NONE><<<hgrd, 128>>>(t0, w_d2, b_d2, out_delta);
    head_conv3<ACT_SIG ><<<hgrd, 128>>>(t1, w_w2, b_w2, out_wgt);
}

// round 11
// speedup vs baseline: 1.5495x; 1.5495x over previous
#include <cuda_runtime.h>
#include <cuda_bf16.h>
#include <math.h>

// ---------------------------------------------------------------------------
// RAFT-SLAM update block, fp32 implicit-GEMM, packed fma.rn.f32x2 along M.
// R8 post-mortem: old design was smem-wavefront bound (L1=90.6%) due to
// duplicated A pairs + 16-way STS conflict in A staging. Now:
//   - accumulate (m, m+1) cout-row pairs: A pair = 2 consecutive smem floats
//   - B values duplicated in REGISTERS (mov.b64), zero extra smem traffic
//   - As rows padded +4 floats: staging conflict 16-way -> 2-way
// ---------------------------------------------------------------------------

#define Hh 60
#define Ww 80
#define HW 4800
#define BN 24

#define ACT_NONE 0
#define ACT_RELU 1
#define ACT_SIG  2
#define ACT_GRUQ 3   // h' = (1-z)*h + z*tanh(acc + qpart)

typedef unsigned long long u64;

// ---------------- scratch (static device memory; no cudaMalloc allowed) ----
__device__ float g_hx[BN * 448 * HW];   // [h or r*h | inp | corrfeat | flowfeat]
__device__ float g_t0[BN * 128 * HW];   // ce1 out, later d1 out
__device__ float g_t1[BN * 128 * HW];   // fe1 out, later w1 out
__device__ float g_z [BN * 128 * HW];
__device__ float g_r [BN * 128 * HW];
__device__ float g_q [BN * 128 * HW];   // q partial (x-channel contribution)
__device__ float g_zbias[128];          // zero-initialized per CUDA semantics

// packed 2x fp32 FMA (sm_103a; ptxas never auto-fuses this from C++)
__device__ __forceinline__ u64 ffma2(u64 a, u64 b, u64 c) {
    u64 d;
    asm("fma.rn.f32x2 %0, %1, %2, %3;" : "=l"(d) : "l"(a), "l"(b), "l"(c));
    return d;
}
__device__ __forceinline__ u64 dup2(float x) {      // (x,x) pair, 1 mov.b64
    u64 d;
    asm("mov.b64 %0, {%1, %1};" : "=l"(d) : "f"(x));
    return d;
}
__device__ __forceinline__ float lo32f(u64 v) { return __uint_as_float((unsigned)(v)); }
__device__ __forceinline__ float hi32f(u64 v) { return __uint_as_float((unsigned)(v >> 32)); }

// ---------------- job descriptor -------------------------------------------
struct Job {
    const float* wt;      // weight matrix base
    const float* bias;
    float*       out;
    int Cin;              // input channels this job consumes
    int in_choff;         // channel offset into shared input tensor
    int out_choff;        // channel offset into output tensor
    int wk_stride;        // weight row stride (full K of original conv)
    int wk_off;           // k offset into weight row
    int act;
};

// ---------------- implicit GEMM conv ---------------------------------------
// Tiles: TM=128 (cout), TN=128 (pixels), TK=16. 256 threads, 8x8 microtile.
// acc2[i][j] packs cout rows (tr*8+2i, tr*8+2i+1) for pixel tc*8+j.
#define TM 128
#define TN 128
#define TK 16
#define APAD 4   // As row pad (floats): breaks staging bank conflict, keeps 16B align

template<int KH, int KW, int PAD>
__global__ __launch_bounds__(256, 2)
void conv_igemm(const float* __restrict__ in,
                Job j0, Job j1, Job j2,
                int Cout, int in_bstride, int out_bstride,
                const float* __restrict__ zbuf,
                const float* __restrict__ qbuf,
                const float* __restrict__ hbuf)
{
    const Job jb = (blockIdx.y == 0) ? j0 : ((blockIdx.y == 1) ? j1 : j2);
    const int K  = jb.Cin * KH * KW;
    const int bn = blockIdx.z;
    const int n0 = blockIdx.x * TN;
    const float* wt  = jb.wt;
    const float* inb = in + (size_t)bn * in_bstride + (size_t)jb.in_choff * HW;

    __shared__ __align__(16) float As[2][TK][TM + APAD];  // ~16.5KB
    __shared__ __align__(16) float Bs[2][TK][TN];         // 16KB

    const int tid = threadIdx.x;

    // B-load mapping: element j (0..7): k_local = j*2 + tid/128, n_local = tid%128
    const int bn_local = tid & 127;
    const int bk_base  = tid >> 7;
    const int n_glob   = n0 + bn_local;
    const int py = n_glob / Ww;
    const int px = n_glob % Ww;
    const bool nvalid = (n_glob < HW);

    // halo validity bitmasks
    unsigned rowmask = 0, colmask = 0;
    #pragma unroll
    for (int t = 0; t < KH; t++) {
        int iy = py + t - PAD;
        if (iy >= 0 && iy < Hh) rowmask |= (1u << t);
    }
    #pragma unroll
    for (int t = 0; t < KW; t++) {
        int ix = px + t - PAD;
        if (ix >= 0 && ix < Ww) colmask |= (1u << t);
    }
    if (!nvalid) { rowmask = 0; colmask = 0; }
    const float* ibase = inb + (py - PAD) * Ww + (px - PAD);

    // A-load mapping: element j (0..7): k_local = tid%16, m_local = j*16 + tid/16
    const int ak      = tid & 15;
    const int am_base = tid >> 4;

    // compute mapping
    const int tr = tid >> 4;   // cout rows tr*8..+7 (as 4 pairs)
    const int tc = tid & 15;   // pixels tc*8..+7

    // acc2[i][j]: (row tr*8+2i, row tr*8+2i+1) x pixel tc*8+j
    u64 acc2[4][8];
    #pragma unroll
    for (int i = 0; i < 4; i++)
        #pragma unroll
        for (int j = 0; j < 8; j++) acc2[i][j] = 0ull;

    auto gatherA = [&](int k0, float (&ar)[8]) {
        #pragma unroll
        for (int j = 0; j < 8; j++) {
            int m = am_base + j * 16;
            int k = k0 + ak;
            float v = 0.f;
            if (k < K && m < Cout)
                v = wt[(size_t)m * jb.wk_stride + jb.wk_off + k];
            ar[j] = v;
        }
    };
    auto gatherB = [&](int k0, float (&br)[8]) {
        #pragma unroll
        for (int j = 0; j < 8; j++) {
            int k = k0 + bk_base + j * 2;
            float v = 0.f;
            if (KH == 1 && KW == 1) {
                if (k < K && nvalid)
                    v = ibase[(size_t)k * HW];
            } else {
                int ci  = k / (KH * KW);
                int rem = k - ci * (KH * KW);
                int ky  = rem / KW;
                int kx  = rem - ky * KW;
                bool ok = (k < K) & (((rowmask >> ky) & (colmask >> kx)) & 1u);
                if (ok)
                    v = ibase[(size_t)ci * HW + ky * Ww + kx];
            }
            br[j] = v;
        }
    };
    auto stage = [&](int buf, const float (&ar)[8], const float (&br)[8]) {
        #pragma unroll
        for (int j = 0; j < 8; j++)
            As[buf][ak][am_base + j * 16] = ar[j];
        #pragma unroll
        for (int j = 0; j < 8; j++)
            Bs[buf][bk_base + j * 2][bn_local] = br[j];
    };

    // ---- prologue -----------------------------------------------------------
    {
        float ar[8], br[8];
        gatherA(0, ar); gatherB(0, br);
        stage(0, ar, br);
    }
    __syncthreads();

    int buf = 0;
    for (int k0 = 0; k0 < K; k0 += TK) {
        const bool more = (k0 + TK < K);
        float ar[8], br[8];
        if (more) { gatherA(k0 + TK, ar); gatherB(k0 + TK, br); }

        // ---- compute: 16 k-steps x (4x8) FFMA2
        #pragma unroll
        for (int kk = 0; kk < TK; kk++) {
            // A: 8 consecutive floats = 4 (m,m+1) u64 pairs, 2x LDS.128
            const ulonglong2* ap2 = (const ulonglong2*)&As[buf][kk][tr * 8];
            ulonglong2 a01 = ap2[0], a23 = ap2[1];
            u64 am[4] = {a01.x, a01.y, a23.x, a23.y};
            const float4* bp4 = (const float4*)&Bs[buf][kk][tc * 8];
            // half 1: pixels 0..3
            {
                float4 b0 = bp4[0];
                u64 d0 = dup2(b0.x), d1 = dup2(b0.y), d2 = dup2(b0.z), d3 = dup2(b0.w);
                #pragma unroll
                for (int i = 0; i < 4; i++) {
                    acc2[i][0] = ffma2(am[i], d0, acc2[i][0]);
                    acc2[i][1] = ffma2(am[i], d1, acc2[i][1]);
                    acc2[i][2] = ffma2(am[i], d2, acc2[i][2]);
                    acc2[i][3] = ffma2(am[i], d3, acc2[i][3]);
                }
            }
            // half 2: pixels 4..7
            {
                float4 b1 = bp4[1];
                u64 d4 = dup2(b1.x), d5 = dup2(b1.y), d6 = dup2(b1.z), d7 = dup2(b1.w);
                #pragma unroll
                for (int i = 0; i < 4; i++) {
                    acc2[i][4] = ffma2(am[i], d4, acc2[i][4]);
                    acc2[i][5] = ffma2(am[i], d5, acc2[i][5]);
                    acc2[i][6] = ffma2(am[i], d6, acc2[i][6]);
                    acc2[i][7] = ffma2(am[i], d7, acc2[i][7]);
                }
            }
        }

        if (more) stage(buf ^ 1, ar, br);
        __syncthreads();
        buf ^= 1;
    }

    // ---- epilogue: bias + activation (+GRU fusion) + float4 store ----------
    // acc2[i][j]: lo = row tr*8+2i, hi = row tr*8+2i+1, pixel tc*8+j
    float* outb = jb.out + (size_t)bn * out_bstride + (size_t)jb.out_choff * HW;
    const int act = jb.act;
    #pragma unroll
    for (int i = 0; i < 4; i++) {
        #pragma unroll
        for (int h = 0; h < 2; h++) {
            int m = tr * 8 + i * 2 + h;
            if (m >= Cout) continue;
            float bv = jb.bias[m];
            #pragma unroll
            for (int jj = 0; jj < 2; jj++) {
                int n = n0 + tc * 8 + jj * 4;
                if (n + 3 >= HW) continue;
                float4 v;
                float* vp = (float*)&v;
                #pragma unroll
                for (int j = 0; j < 4; j++) {
                    u64 p = acc2[i][jj * 4 + j];
                    float x = (h ? hi32f(p) : lo32f(p)) + bv;
                    if (act == ACT_RELU)      x = fmaxf(x, 0.f);
                    else if (act == ACT_SIG)  x = 1.f / (1.f + expf(-x));
                    else if (act == ACT_GRUQ) {
                        size_t e = (size_t)bn * (128 * HW) + (size_t)m * HW + (n + j);
                        float q = tanhf(x + qbuf[e]);
                        float z = zbuf[e];
                        x = (1.f - z) * hbuf[e] + z * q;
                    }
                    vp[j] = x;
                }
                *(float4*)&outb[(size_t)m * HW + n] = v;
            }
        }
    }
}

// ---------------- 128 -> 3 head conv (3x3, pad 1), fused NHWC transpose ----
template<int ACT>
__global__ __launch_bounds__(128)
void head_conv3(const float* __restrict__ in, const float* __restrict__ wt,
                const float* __restrict__ bias, float* __restrict__ out)
{
    __shared__ float ws[3 * 128 * 9];
    for (int i = threadIdx.x; i < 3 * 128 * 9; i += blockDim.x) ws[i] = wt[i];
    __syncthreads();

    const int bn = blockIdx.y;
    const int p  = blockIdx.x * blockDim.x + threadIdx.x;
    if (p >= HW) return;
    const int y = p / Ww, x = p % Ww;
    const float* inb = in + (size_t)bn * 128 * HW;

    float a0 = bias[0], a1 = bias[1], a2 = bias[2];
    for (int ci = 0; ci < 128; ci++) {
        const float* ip = inb + (size_t)ci * HW;
        #pragma unroll
        for (int ky = 0; ky < 3; ky++) {
            int iy = y + ky - 1;
            if (iy < 0 || iy >= Hh) continue;
            #pragma unroll
            for (int kx = 0; kx < 3; kx++) {
                int ix = x + kx - 1;
                if (ix < 0 || ix >= Ww) continue;
                float v = __ldg(&ip[iy * Ww + ix]);
                int t = ci * 9 + ky * 3 + kx;
                a0 = fmaf(ws[t],            v, a0);
                a1 = fmaf(ws[1152 + t],     v, a1);
                a2 = fmaf(ws[2 * 1152 + t], v, a2);
            }
        }
    }
    if (ACT == ACT_SIG) {
        a0 = 1.f / (1.f + expf(-a0));
        a1 = 1.f / (1.f + expf(-a1));
        a2 = 1.f / (1.f + expf(-a2));
    }
    size_t o = ((size_t)bn * HW + p) * 3;   // NHWC
    out[o + 0] = a0; out[o + 1] = a1; out[o + 2] = a2;
}

// ---------------- elementwise kernels ---------------------------------------
__global__ void pack_hx_kernel(const float* __restrict__ net,
                               const float* __restrict__ inp)
{
    int idx = blockIdx.x * blockDim.x + threadIdx.x;
    const int per = 128 * HW;
    if (idx >= BN * per) return;
    int bn = idx / per;
    int r  = idx - bn * per;
    float* hx = g_hx + (size_t)bn * 448 * HW;
    hx[r]            = net[idx];
    hx[128 * HW + r] = inp[idx];
}

__global__ void rh_kernel(const float* __restrict__ net)
{
    int idx = blockIdx.x * blockDim.x + threadIdx.x;
    const int per = 128 * HW;
    if (idx >= BN * per) return;
    int bn = idx / per;
    int r  = idx - bn * per;
    g_hx[(size_t)bn * 448 * HW + r] = g_r[idx] * net[idx];
}

// ---------------- launch graph ----------------------------------------------
static inline Job mkjob(const float* w, const float* b, float* o,
                        int cin, int ichoff, int ochoff,
                        int wks, int wko, int act)
{
    Job j; j.wt = w; j.bias = b; j.out = o; j.Cin = cin; j.in_choff = ichoff;
    j.out_choff = ochoff; j.wk_stride = wks; j.wk_off = wko; j.act = act;
    return j;
}

extern "C" void kernel_launch(void* const* d_in, const int* in_sizes, int n_in,
                              void* d_out, int out_size)
{
    const float* net   = (const float*)d_in[0];
    const float* inp   = (const float*)d_in[1];
    const float* corr  = (const float*)d_in[2];
    const float* flow  = (const float*)d_in[3];
    const float* w_ce1 = (const float*)d_in[4];   const float* b_ce1 = (const float*)d_in[5];
    const float* w_ce2 = (const float*)d_in[6];   const float* b_ce2 = (const float*)d_in[7];
    const float* w_fe1 = (const float*)d_in[8];   const float* b_fe1 = (const float*)d_in[9];
    const float* w_fe2 = (const float*)d_in[10];  const float* b_fe2 = (const float*)d_in[11];
    const float* w_z   = (const float*)d_in[12];  const float* b_z   = (const float*)d_in[13];
    const float* w_r   = (const float*)d_in[14];  const float* b_r   = (const float*)d_in[15];
    const float* w_q   = (const float*)d_in[16];  const float* b_q   = (const float*)d_in[17];
    const float* w_d1  = (const float*)d_in[18];  const float* b_d1  = (const float*)d_in[19];
    const float* w_d2  = (const float*)d_in[20];  const float* b_d2  = (const float*)d_in[21];
    const float* w_w1  = (const float*)d_in[22];  const float* b_w1  = (const float*)d_in[23];
    const float* w_w2  = (const float*)d_in[24];  const float* b_w2  = (const float*)d_in[25];

    float* out_net   = (float*)d_out;                       // (BN,128,H,W)
    float* out_delta = out_net + (size_t)BN * 128 * HW;     // (BN,H,W,3)
    float* out_wgt   = out_delta + (size_t)BN * 3 * HW;     // (BN,H,W,3)

    float *hx, *t0, *t1, *zb, *rb, *qb, *zbias;
    cudaGetSymbolAddress((void**)&hx, g_hx);
    cudaGetSymbolAddress((void**)&t0, g_t0);
    cudaGetSymbolAddress((void**)&t1, g_t1);
    cudaGetSymbolAddress((void**)&zb, g_z);
    cudaGetSymbolAddress((void**)&rb, g_r);
    cudaGetSymbolAddress((void**)&qb, g_q);
    cudaGetSymbolAddress((void**)&zbias, g_zbias);

    const dim3 blk(256);
    const int  NX = (HW + TN - 1) / TN;          // 38
    const dim3 g1(NX, 1, BN);
    const dim3 g2(NX, 2, BN);
    const dim3 g3(NX, 3, BN);
    const int EW = 256;
    const int NE = BN * 128 * HW;
    const int EG = (NE + EW - 1) / EW;

    // encoders
    {
        Job j = mkjob(w_ce1, b_ce1, t0, 197, 0, 0, 197, 0, ACT_RELU);
        conv_igemm<1,1,0><<<g1, blk>>>(corr, j, j, j, 128, 197*HW, 128*HW, 0, 0, 0);
    }
    {
        Job j = mkjob(w_ce2, b_ce2, hx, 128, 0, 256, 1152, 0, ACT_RELU);
        conv_igemm<3,3,1><<<g1, blk>>>(t0, j, j, j, 128, 128*HW, 448*HW, 0, 0, 0);
    }
    {
        Job j = mkjob(w_fe1, b_fe1, t1, 3, 0, 0, 147, 0, ACT_RELU);
        conv_igemm<7,7,3><<<g1, blk>>>(flow, j, j, j, 128, 3*HW, 128*HW, 0, 0, 0);
    }
    {
        Job j = mkjob(w_fe2, b_fe2, hx, 128, 0, 384, 1152, 0, ACT_RELU);
        conv_igemm<3,3,1><<<g1, blk>>>(t1, j, j, j, 64, 128*HW, 448*HW, 0, 0, 0);
    }

    // hx[0:128]=h, hx[128:256]=inp
    pack_hx_kernel<<<EG, EW>>>(net, inp);

    // gates: z, r (K=4032) + q-partial over x channels (K=2880) in ONE launch
    {
        Job jz = mkjob(w_z, b_z, zb, 448, 0, 0, 4032, 0, ACT_SIG);
        Job jr = mkjob(w_r, b_r, rb, 448, 0, 0, 4032, 0, ACT_SIG);
        Job jq = mkjob(w_q, b_q, qb, 320, 128, 0, 4032, 1152, ACT_NONE);
        conv_igemm<3,3,1><<<g3, blk>>>(hx, jz, jr, jq, 128, 448*HW, 128*HW, 0, 0, 0);
    }
    rh_kernel<<<EG, EW>>>(net);                   // hx[0:128] = r*h

    // q completion over r*h (K=1152) with fused GRU output -> out_net
    {
        Job j = mkjob(w_q, zbias, out_net, 128, 0, 0, 4032, 0, ACT_GRUQ);
        conv_igemm<3,3,1><<<g1, blk>>>(hx, j, j, j, 128, 448*HW, 128*HW, zb, qb, net);
    }

    // heads: d1 and w1 share input h' -> one dual launch
    {
        Job jd = mkjob(w_d1, b_d1, t0, 128, 0, 0, 1152, 0, ACT_RELU);
        Job jw = mkjob(w_w1, b_w1, t1, 128, 0, 0, 1152, 0, ACT_RELU);
        conv_igemm<3,3,1><<<g2, blk>>>(out_net, jd, jw, jw, 128, 128*HW, 128*HW, 0, 0, 0);
    }

    dim3 hgrd((HW + 127) / 128, BN);
    head_conv3<ACT_NONE><<<hgrd, 128>>>(t0, w_d2, b_d2, out_delta);
    head_conv3<ACT_SIG ><<<hgrd, 128>>>(t1, w_w2, b_w2, out_wgt);
}

// round 14
// speedup vs baseline: 2.6512x; 1.7110x over previous
#include <cuda_runtime.h>
#include <cuda_bf16.h>
#include <math.h>

// ---------------------------------------------------------------------------
// RAFT-SLAM update block: implicit-GEMM convs on TF32 tensor cores via
// mma.sync.m16n8k8 (fp32 accumulate). R11 post-mortem: FFMA2 design was
// co-bound on smem wavefronts (L1=77.9%) and fma (58.9%); tensor pipe idle.
// mma.sync gives 16x fewer math issues and 5.3x fewer smem wavefronts.
// Inputs rounded fp32->tf32 with cvt.rna at staging (rel_err ~3e-4 expected).
// ---------------------------------------------------------------------------

#define Hh 60
#define Ww 80
#define HW 4800
#define BN 24

#define ACT_NONE 0
#define ACT_RELU 1
#define ACT_SIG  2
#define ACT_GRUQ 3   // h' = (1-z)*h + z*tanh(acc + qpart)

// ---------------- scratch (static device memory; no cudaMalloc allowed) ----
__device__ float g_hx[BN * 448 * HW];   // [h or r*h | inp | corrfeat | flowfeat]
__device__ float g_t0[BN * 128 * HW];   // ce1 out, later d1 out
__device__ float g_t1[BN * 128 * HW];   // fe1 out, later w1 out
__device__ float g_z [BN * 128 * HW];
__device__ float g_r [BN * 128 * HW];
__device__ float g_q [BN * 128 * HW];   // q partial (x-channel contribution)
__device__ float g_zbias[128];          // zero-initialized per CUDA semantics

__device__ __forceinline__ float to_tf32(float x) {
    float y;
    asm("cvt.rna.tf32.f32 %0, %1;" : "=f"(y) : "f"(x));
    return y;
}

#define MMA_TF32(d, a, b) \
    asm volatile("mma.sync.aligned.m16n8k8.row.col.f32.tf32.tf32.f32 " \
        "{%0,%1,%2,%3}, {%4,%5,%6,%7}, {%8,%9}, {%0,%1,%2,%3};" \
        : "+f"(d[0]), "+f"(d[1]), "+f"(d[2]), "+f"(d[3]) \
        : "r"(a[0]), "r"(a[1]), "r"(a[2]), "r"(a[3]), "r"(b[0]), "r"(b[1]))

// ---------------- job descriptor -------------------------------------------
struct Job {
    const float* wt;      // weight matrix base
    const float* bias;
    float*       out;
    int Cin;              // input channels this job consumes
    int in_choff;         // channel offset into shared input tensor
    int out_choff;        // channel offset into output tensor
    int wk_stride;        // weight row stride (full K of original conv)
    int wk_off;           // k offset into weight row
    int act;
};

// ---------------- implicit GEMM conv (tf32 mma.sync) ------------------------
// Block 256 thr = 8 warps (2 m x 4 n). Tile M=128 x N=128, TK=16 (2 k-frags).
// Warp tile 64x32 = 4x4 m16n8k8 atoms. Double-buffered smem, +4 padding
// makes both fragment-load patterns bank-conflict-free.
#define TM 128
#define TN 128
#define TK 16
#define PADF 4

template<int KH, int KW, int PAD>
__global__ __launch_bounds__(256, 2)
void conv_mma(const float* __restrict__ in,
              Job j0, Job j1, Job j2,
              int Cout, int in_bstride, int out_bstride,
              const float* __restrict__ zbuf,
              const float* __restrict__ qbuf,
              const float* __restrict__ hbuf)
{
    const Job jb = (blockIdx.y == 0) ? j0 : ((blockIdx.y == 1) ? j1 : j2);
    const int K  = jb.Cin * KH * KW;
    const int bn = blockIdx.z;
    const int n0 = blockIdx.x * TN;
    const float* wt  = jb.wt;
    const float* inb = in + (size_t)bn * in_bstride + (size_t)jb.in_choff * HW;

    __shared__ __align__(16) float As[2][TK][TM + PADF];  // ~16.9KB
    __shared__ __align__(16) float Bs[2][TK][TN + PADF];  // ~16.9KB

    const int tid  = threadIdx.x;
    const int warp = tid >> 5;
    const int lane = tid & 31;
    const int g    = lane >> 2;      // group id 0..7
    const int tg   = lane & 3;       // thread-in-group 0..3
    const int wm   = (warp >> 2) * 64;   // warp M offset (0 or 64)
    const int wn   = (warp & 3) * 32;    // warp N offset (0,32,64,96)

    // ---- gather mappings ---------------------------------------------------
    const int bn_local = tid & 127;
    const int bk_base  = tid >> 7;
    const int n_glob   = n0 + bn_local;
    const int py = n_glob / Ww;
    const int px = n_glob % Ww;
    const bool nvalid = (n_glob < HW);

    unsigned rowmask = 0, colmask = 0;
    #pragma unroll
    for (int t = 0; t < KH; t++) {
        int iy = py + t - PAD;
        if (iy >= 0 && iy < Hh) rowmask |= (1u << t);
    }
    #pragma unroll
    for (int t = 0; t < KW; t++) {
        int ix = px + t - PAD;
        if (ix >= 0 && ix < Ww) colmask |= (1u << t);
    }
    if (!nvalid) { rowmask = 0; colmask = 0; }
    const float* ibase = inb + (py - PAD) * Ww + (px - PAD);

    const int ak      = tid & 15;    // A-stage k row
    const int am_base = tid >> 4;    // A-stage m base

    // accumulators: d[m_atom][n_atom][4]
    float d[4][4][4];
    #pragma unroll
    for (int i = 0; i < 4; i++)
        #pragma unroll
        for (int j = 0; j < 4; j++)
            #pragma unroll
            for (int c = 0; c < 4; c++) d[i][j][c] = 0.f;

    auto gatherA = [&](int k0, float (&ar)[8]) {
        #pragma unroll
        for (int j = 0; j < 8; j++) {
            int m = am_base + j * 16;
            int k = k0 + ak;
            float v = 0.f;
            if (k < K && m < Cout)
                v = wt[(size_t)m * jb.wk_stride + jb.wk_off + k];
            ar[j] = to_tf32(v);
        }
    };
    auto gatherB = [&](int k0, float (&br)[8]) {
        #pragma unroll
        for (int j = 0; j < 8; j++) {
            int k = k0 + bk_base + j * 2;
            float v = 0.f;
            if (KH == 1 && KW == 1) {
                if (k < K && nvalid)
                    v = ibase[(size_t)k * HW];
            } else {
                int ci  = k / (KH * KW);
                int rem = k - ci * (KH * KW);
                int ky  = rem / KW;
                int kx  = rem - ky * KW;
                bool ok = (k < K) & (((rowmask >> ky) & (colmask >> kx)) & 1u);
                if (ok)
                    v = ibase[(size_t)ci * HW + ky * Ww + kx];
            }
            br[j] = to_tf32(v);
        }
    };
    auto stage = [&](int buf, const float (&ar)[8], const float (&br)[8]) {
        #pragma unroll
        for (int j = 0; j < 8; j++)
            As[buf][ak][am_base + j * 16] = ar[j];
        #pragma unroll
        for (int j = 0; j < 8; j++)
            Bs[buf][bk_base + j * 2][bn_local] = br[j];
    };

    // ---- prologue -----------------------------------------------------------
    {
        float ar[8], br[8];
        gatherA(0, ar); gatherB(0, br);
        stage(0, ar, br);
    }
    __syncthreads();

    int buf = 0;
    for (int k0 = 0; k0 < K; k0 += TK) {
        const bool more = (k0 + TK < K);
        float ar[8], br[8];
        if (more) { gatherA(k0 + TK, ar); gatherB(k0 + TK, br); }

        // ---- compute: 2 k-frags of 8, 16 mma each -------------------------
        #pragma unroll
        for (int ks = 0; ks < TK; ks += 8) {
            // B fragments: b[n_atom][2]
            unsigned bf[4][2];
            #pragma unroll
            for (int j = 0; j < 4; j++) {
                int col = wn + j * 8 + g;
                bf[j][0] = __float_as_uint(Bs[buf][ks + tg    ][col]);
                bf[j][1] = __float_as_uint(Bs[buf][ks + tg + 4][col]);
            }
            #pragma unroll
            for (int i = 0; i < 4; i++) {
                int r0 = wm + i * 16 + g;
                unsigned af[4];
                af[0] = __float_as_uint(As[buf][ks + tg    ][r0]);
                af[1] = __float_as_uint(As[buf][ks + tg    ][r0 + 8]);
                af[2] = __float_as_uint(As[buf][ks + tg + 4][r0]);
                af[3] = __float_as_uint(As[buf][ks + tg + 4][r0 + 8]);
                #pragma unroll
                for (int j = 0; j < 4; j++)
                    MMA_TF32(d[i][j], af, bf[j]);
            }
        }

        if (more) stage(buf ^ 1, ar, br);
        __syncthreads();
        buf ^= 1;
    }

    // ---- epilogue: bias + activation (+GRU fusion) + float2 stores --------
    // d[i][j]: c0,c1 -> (row wm+i*16+g,   cols wn+j*8+tg*2, +1)
    //          c2,c3 -> (row wm+i*16+g+8, same cols)
    float* outb = jb.out + (size_t)bn * out_bstride + (size_t)jb.out_choff * HW;
    const int act = jb.act;
    #pragma unroll
    for (int i = 0; i < 4; i++) {
        #pragma unroll
        for (int h = 0; h < 2; h++) {
            int m = wm + i * 16 + g + h * 8;
            if (m >= Cout) continue;
            float bv = jb.bias[m];
            #pragma unroll
            for (int j = 0; j < 4; j++) {
                int n = n0 + wn + j * 8 + tg * 2;
                if (n >= HW) continue;     // n even, HW even -> n+1 < HW too
                float2 v;
                #pragma unroll
                for (int c = 0; c < 2; c++) {
                    float x = d[i][j][h * 2 + c] + bv;
                    if (act == ACT_RELU)      x = fmaxf(x, 0.f);
                    else if (act == ACT_SIG)  x = 1.f / (1.f + expf(-x));
                    else if (act == ACT_GRUQ) {
                        size_t e = (size_t)bn * (128 * HW) + (size_t)m * HW + (n + c);
                        float q = tanhf(x + qbuf[e]);
                        float z = zbuf[e];
                        x = (1.f - z) * hbuf[e] + z * q;
                    }
                    ((float*)&v)[c] = x;
                }
                *(float2*)&outb[(size_t)m * HW + n] = v;
            }
        }
    }
}

// ---------------- 128 -> 3 head conv (3x3, pad 1), fused NHWC transpose ----
template<int ACT>
__global__ __launch_bounds__(128)
void head_conv3(const float* __restrict__ in, const float* __restrict__ wt,
                const float* __restrict__ bias, float* __restrict__ out)
{
    __shared__ float ws[3 * 128 * 9];
    for (int i = threadIdx.x; i < 3 * 128 * 9; i += blockDim.x) ws[i] = wt[i];
    __syncthreads();

    const int bn = blockIdx.y;
    const int p  = blockIdx.x * blockDim.x + threadIdx.x;
    if (p >= HW) return;
    const int y = p / Ww, x = p % Ww;
    const float* inb = in + (size_t)bn * 128 * HW;

    float a0 = bias[0], a1 = bias[1], a2 = bias[2];
    for (int ci = 0; ci < 128; ci++) {
        const float* ip = inb + (size_t)ci * HW;
        #pragma unroll
        for (int ky = 0; ky < 3; ky++) {
            int iy = y + ky - 1;
            if (iy < 0 || iy >= Hh) continue;
            #pragma unroll
            for (int kx = 0; kx < 3; kx++) {
                int ix = x + kx - 1;
                if (ix < 0 || ix >= Ww) continue;
                float v = __ldg(&ip[iy * Ww + ix]);
                int t = ci * 9 + ky * 3 + kx;
                a0 = fmaf(ws[t],            v, a0);
                a1 = fmaf(ws[1152 + t],     v, a1);
                a2 = fmaf(ws[2 * 1152 + t], v, a2);
            }
        }
    }
    if (ACT == ACT_SIG) {
        a0 = 1.f / (1.f + expf(-a0));
        a1 = 1.f / (1.f + expf(-a1));
        a2 = 1.f / (1.f + expf(-a2));
    }
    size_t o = ((size_t)bn * HW + p) * 3;   // NHWC
    out[o + 0] = a0; out[o + 1] = a1; out[o + 2] = a2;
}

// ---------------- elementwise kernels ---------------------------------------
__global__ void pack_hx_kernel(const float* __restrict__ net,
                               const float* __restrict__ inp)
{
    int idx = blockIdx.x * blockDim.x + threadIdx.x;
    const int per = 128 * HW;
    if (idx >= BN * per) return;
    int bn = idx / per;
    int r  = idx - bn * per;
    float* hx = g_hx + (size_t)bn * 448 * HW;
    hx[r]            = net[idx];
    hx[128 * HW + r] = inp[idx];
}

__global__ void rh_kernel(const float* __restrict__ net)
{
    int idx = blockIdx.x * blockDim.x + threadIdx.x;
    const int per = 128 * HW;
    if (idx >= BN * per) return;
    int bn = idx / per;
    int r  = idx - bn * per;
    g_hx[(size_t)bn * 448 * HW + r] = g_r[idx] * net[idx];
}

// ---------------- launch graph ----------------------------------------------
static inline Job mkjob(const float* w, const float* b, float* o,
                        int cin, int ichoff, int ochoff,
                        int wks, int wko, int act)
{
    Job j; j.wt = w; j.bias = b; j.out = o; j.Cin = cin; j.in_choff = ichoff;
    j.out_choff = ochoff; j.wk_stride = wks; j.wk_off = wko; j.act = act;
    return j;
}

extern "C" void kernel_launch(void* const* d_in, const int* in_sizes, int n_in,
                              void* d_out, int out_size)
{
    const float* net   = (const float*)d_in[0];
    const float* inp   = (const float*)d_in[1];
    const float* corr  = (const float*)d_in[2];
    const float* flow  = (const float*)d_in[3];
    const float* w_ce1 = (const float*)d_in[4];   const float* b_ce1 = (const float*)d_in[5];
    const float* w_ce2 = (const float*)d_in[6];   const float* b_ce2 = (const float*)d_in[7];
    const float* w_fe1 = (const float*)d_in[8];   const float* b_fe1 = (const float*)d_in[9];
    const float* w_fe2 = (const float*)d_in[10];  const float* b_fe2 = (const float*)d_in[11];
    const float* w_z   = (const float*)d_in[12];  const float* b_z   = (const float*)d_in[13];
    const float* w_r   = (const float*)d_in[14];  const float* b_r   = (const float*)d_in[15];
    const float* w_q   = (const float*)d_in[16];  const float* b_q   = (const float*)d_in[17];
    const float* w_d1  = (const float*)d_in[18];  const float* b_d1  = (const float*)d_in[19];
    const float* w_d2  = (const float*)d_in[20];  const float* b_d2  = (const float*)d_in[21];
    const float* w_w1  = (const float*)d_in[22];  const float* b_w1  = (const float*)d_in[23];
    const float* w_w2  = (const float*)d_in[24];  const float* b_w2  = (const float*)d_in[25];

    float* out_net   = (float*)d_out;                       // (BN,128,H,W)
    float* out_delta = out_net + (size_t)BN * 128 * HW;     // (BN,H,W,3)
    float* out_wgt   = out_delta + (size_t)BN * 3 * HW;     // (BN,H,W,3)

    float *hx, *t0, *t1, *zb, *rb, *qb, *zbias;
    cudaGetSymbolAddress((void**)&hx, g_hx);
    cudaGetSymbolAddress((void**)&t0, g_t0);
    cudaGetSymbolAddress((void**)&t1, g_t1);
    cudaGetSymbolAddress((void**)&zb, g_z);
    cudaGetSymbolAddress((void**)&rb, g_r);
    cudaGetSymbolAddress((void**)&qb, g_q);
    cudaGetSymbolAddress((void**)&zbias, g_zbias);

    const dim3 blk(256);
    const int  NX = (HW + TN - 1) / TN;          // 38
    const dim3 g1(NX, 1, BN);
    const dim3 g2(NX, 2, BN);
    const dim3 g3(NX, 3, BN);
    const int EW = 256;
    const int NE = BN * 128 * HW;
    const int EG = (NE + EW - 1) / EW;

    // encoders
    {
        Job j = mkjob(w_ce1, b_ce1, t0, 197, 0, 0, 197, 0, ACT_RELU);
        conv_mma<1,1,0><<<g1, blk>>>(corr, j, j, j, 128, 197*HW, 128*HW, 0, 0, 0);
    }
    {
        Job j = mkjob(w_ce2, b_ce2, hx, 128, 0, 256, 1152, 0, ACT_RELU);
        conv_mma<3,3,1><<<g1, blk>>>(t0, j, j, j, 128, 128*HW, 448*HW, 0, 0, 0);
    }
    {
        Job j = mkjob(w_fe1, b_fe1, t1, 3, 0, 0, 147, 0, ACT_RELU);
        conv_mma<7,7,3><<<g1, blk>>>(flow, j, j, j, 128, 3*HW, 128*HW, 0, 0, 0);
    }
    {
        Job j = mkjob(w_fe2, b_fe2, hx, 128, 0, 384, 1152, 0, ACT_RELU);
        conv_mma<3,3,1><<<g1, blk>>>(t1, j, j, j, 64, 128*HW, 448*HW, 0, 0, 0);
    }

    // hx[0:128]=h, hx[128:256]=inp
    pack_hx_kernel<<<EG, EW>>>(net, inp);

    // gates: z, r (K=4032) + q-partial over x channels (K=2880) in ONE launch
    {
        Job jz = mkjob(w_z, b_z, zb, 448, 0, 0, 4032, 0, ACT_SIG);
        Job jr = mkjob(w_r, b_r, rb, 448, 0, 0, 4032, 0, ACT_SIG);
        Job jq = mkjob(w_q, b_q, qb, 320, 128, 0, 4032, 1152, ACT_NONE);
        conv_mma<3,3,1><<<g3, blk>>>(hx, jz, jr, jq, 128, 448*HW, 128*HW, 0, 0, 0);
    }
    rh_kernel<<<EG, EW>>>(net);                   // hx[0:128] = r*h

    // q completion over r*h (K=1152) with fused GRU output -> out_net
    {
        Job j = mkjob(w_q, zbias, out_net, 128, 0, 0, 4032, 0, ACT_GRUQ);
        conv_mma<3,3,1><<<g1, blk>>>(hx, j, j, j, 128, 448*HW, 128*HW, zb, qb, net);
    }

    // heads: d1 and w1 share input h' -> one dual launch
    {
        Job jd = mkjob(w_d1, b_d1, t0, 128, 0, 0, 1152, 0, ACT_RELU);
        Job jw = mkjob(w_w1, b_w1, t1, 128, 0, 0, 1152, 0, ACT_RELU);
        conv_mma<3,3,1><<<g2, blk>>>(out_net, jd, jw, jw, 128, 128*HW, 128*HW, 0, 0, 0);
    }

    dim3 hgrd((HW + 127) / 128, BN);
    head_conv3<ACT_NONE><<<hgrd, 128>>>(t0, w_d2, b_d2, out_delta);
    head_conv3<ACT_SIG ><<<hgrd, 128>>>(t1, w_w2, b_w2, out_wgt);
}